// round 15
// baseline (speedup 1.0000x reference)
#include <cuda_runtime.h>
#include <cuda_bf16.h>
#include <stdint.h>

// Problem constants
#define N_ROWS 16384
#define F_DIM  256
#define K_SEL  8192   // ceil(0.5 * 16384)
#define NBINS  16384  // top-14-bit buckets of the u64 sort key

#define FIN_BLOCKS 64
#define FIN_THREADS 256

#define AG_BLOCKS 148        // one persistent block per SM
#define AG_THREADS 1024
#define ROW_BYTES 65536      // one A row: 16384 f32

// Output layout (flat f32): X_pooled [K_SEL*F_DIM] | A_pooled [K_SEL*K_SEL] | idx [K_SEL]
#define OUT_X_OFF 0
#define OUT_A_OFF (K_SEL * F_DIM)                       // 2,097,152
#define OUT_I_OFF (OUT_A_OFF + (size_t)K_SEL * K_SEL)   // 69,206,016

// PDL intrinsics (sm_90+): let dependent grid launch early; consumer waits
// for producer completion (incl. memory flush) before touching its data.
__device__ __forceinline__ void pdl_trigger()
{
    asm volatile("griddepcontrol.launch_dependents;" ::: "memory");
}
__device__ __forceinline__ void pdl_wait()
{
    asm volatile("griddepcontrol.wait;" ::: "memory");
}

// Scratch (device globals: no allocations allowed).
// g_hist relies on zero-init at module load; finish_kernel re-zeros it after
// reading, so every launch leaves it zeroed (replay-safe).
__device__ unsigned long long g_keys[N_ROWS];    // per-row sort key
__device__ unsigned long long g_bkeys[N_ROWS];   // keys grouped by bucket
__device__ int g_hist[NBINS];
__device__ int g_base[NBINS];                    // bucket exclusive prefix
__device__ int g_cursor[NBINS];                  // scatter cursors (end after scatter)
__device__ unsigned g_bsum[FIN_BLOCKS];          // per-block bin totals
__device__ int g_idx[K_SEL];

// Monotonic grid barrier ticket. NEVER reset — correct across graph replays
// and ncu kernel replays because the goal is computed per-arrival.
__device__ unsigned long long g_ticket;

__device__ __forceinline__ void grid_sync_fin()
{
    __syncthreads();
    if (threadIdx.x == 0) {
        __threadfence();                               // release my writes
        unsigned long long t = atomicAdd(&g_ticket, 1ull) + 1ull;
        unsigned long long goal =
            ((t + FIN_BLOCKS - 1ull) / FIN_BLOCKS) * FIN_BLOCKS;
        unsigned long long cur;
        do {
            asm volatile("ld.acquire.gpu.u64 %0, [%1];"
                         : "=l"(cur) : "l"(&g_ticket));
        } while (cur < goal);
    }
    __syncthreads();
}

// ---------------------------------------------------------------------------
// Kernel 1 (WIDE): scores = X @ v ; sortable u64 keys; 14-bit histogram.
// One warp per row, lane-strided c = lane + 32*t, EXPLICIT rounded mul +
// rounded add (NO fma), xor shuffle tree — bit-matches the XLA reference
// reduction. key = (~orderedU32(score) << 32) | row : ascending key ==
// descending score, ties -> ascending row (lax.top_k). DO NOT TOUCH THE MATH.
// PDL: trigger at entry so finish_kernel can ramp up concurrently.
// ---------------------------------------------------------------------------
__global__ __launch_bounds__(256) void scores_kernel(
    const float* __restrict__ X, const float* __restrict__ sv)
{
    pdl_trigger();

    int gwarp = (blockIdx.x * blockDim.x + threadIdx.x) >> 5;
    int lane  = threadIdx.x & 31;
    if (gwarp >= N_ROWS) return;

    const float* xr = X + (size_t)gwarp * F_DIM;
    float acc = 0.0f;
#pragma unroll
    for (int t = 0; t < F_DIM / 32; t++) {
        int c = lane + 32 * t;
        acc = __fadd_rn(acc, __fmul_rn(__ldg(xr + c), __ldg(sv + c)));
    }
#pragma unroll
    for (int o = 16; o > 0; o >>= 1)
        acc = __fadd_rn(acc, __shfl_xor_sync(0xFFFFFFFFu, acc, o));

    if (lane == 0) {
        unsigned ub = __float_as_uint(acc);
        unsigned u = (ub & 0x80000000u) ? ~ub : (ub | 0x80000000u);
        unsigned long long key =
            ((unsigned long long)(~u) << 32) | (unsigned)gwarp;
        g_keys[gwarp] = key;
        atomicAdd(&g_hist[(int)(key >> 50)], 1);
    }
}

// ---------------------------------------------------------------------------
// Kernel 2 (PERSISTENT, tiny phases): 64 blocks x 256 threads, co-resident.
//   C: exclusive scan of 16384 bins (+ re-zero g_hist for next launch)
//   D: scatter keys into bucket-grouped order
//   E: exact rank = bucket_base + strict-less count within bucket; emit idx
// Intra-bucket scatter order is atomic-arrival order — harmless: ranking
// compares full unique keys, so the result is deterministic.
// PDL: trigger at entry (lets agather ramp), wait before reading g_hist.
// ---------------------------------------------------------------------------
__global__ __launch_bounds__(FIN_THREADS) void finish_kernel(
    float* __restrict__ out_idx)
{
    pdl_trigger();

    const int tid  = threadIdx.x;
    const int bid  = blockIdx.x;
    const int lane = tid & 31;
    const int wid  = tid >> 5;
    const int gbin = bid * FIN_THREADS + tid;      // 0..16383

    pdl_wait();                                    // scores data now visible

    // ---- Phase C: exclusive scan over 16384 bins -----------------------
    __shared__ unsigned wsum[8], wpre[8];
    __shared__ unsigned bpre_sh;
    unsigned excl;
    {
        unsigned v = (unsigned)g_hist[gbin];
        g_hist[gbin] = 0;                          // re-arm for next launch
        unsigned orig = v;
#pragma unroll
        for (int o = 1; o < 32; o <<= 1) {         // inclusive warp scan
            unsigned n = __shfl_up_sync(0xFFFFFFFFu, v, o);
            if (lane >= o) v += n;
        }
        if (lane == 31) wsum[wid] = v;
        __syncthreads();
        if (wid == 0 && lane < 8) {
            unsigned s = wsum[lane];
#pragma unroll
            for (int o = 1; o < 8; o <<= 1) {
                unsigned n = __shfl_up_sync(0xFFu, s, o);
                if (lane >= o) s += n;
            }
            wpre[lane] = s - wsum[lane];           // exclusive warp prefix
            if (lane == 7) g_bsum[bid] = s;        // block total
        }
        __syncthreads();
        excl = v - orig + wpre[wid];               // exclusive within block
    }
    grid_sync_fin();
    {
        // cross-block prefix: sum of g_bsum[0..bid)
        if (wid == 0) {
            unsigned s1 = (lane < bid) ? g_bsum[lane] : 0u;
            unsigned s2 = (32 + lane < bid) ? g_bsum[32 + lane] : 0u;
            unsigned s = s1 + s2;
#pragma unroll
            for (int o = 16; o > 0; o >>= 1)
                s += __shfl_xor_sync(0xFFFFFFFFu, s, o);
            if (lane == 0) bpre_sh = s;
        }
        __syncthreads();
        int base = (int)(bpre_sh + excl);
        g_base[gbin] = base;
        g_cursor[gbin] = base;
    }
    grid_sync_fin();

    // ---- Phase D: bucket-grouped scatter --------------------------------
    {
        unsigned long long key = g_keys[gbin];
        int b = (int)(key >> 50);
        int pos = atomicAdd(&g_cursor[b], 1);
        g_bkeys[pos] = key;
    }
    grid_sync_fin();

    // ---- Phase E: exact rank + emit -------------------------------------
    {
        unsigned long long key = g_bkeys[gbin];
        int b = (int)(key >> 50);
        int lo = g_base[b];
        int hi = g_cursor[b];                      // == end of bucket b

        int r = lo;
        int j = lo;
        for (; j + 4 <= hi; j += 4) {
            unsigned long long k0 = __ldg(&g_bkeys[j]);
            unsigned long long k1 = __ldg(&g_bkeys[j + 1]);
            unsigned long long k2 = __ldg(&g_bkeys[j + 2]);
            unsigned long long k3 = __ldg(&g_bkeys[j + 3]);
            r += (k0 < key) + (k1 < key) + (k2 < key) + (k3 < key);
        }
        for (; j < hi; j++)
            r += (__ldg(&g_bkeys[j]) < key);

        if (r < K_SEL) {
            int row = (int)(unsigned)(key & 0xFFFFFFFFull);
            g_idx[r] = row;
            out_idx[r] = (float)row;
        }
    }
}

// ---------------------------------------------------------------------------
// Kernel 3 (PERSISTENT, double-buffered TMA): A_pooled[p][q] = A[idx[p]][idx[q]]
// + folded X_pooled[p] = X[idx[p]].
// 148 blocks (1/SM) x 1024 threads. Two 64KB smem row buffers; one producer
// thread prefetches row i+1 via cp.async.bulk (mbarrier complete_tx) while
// all threads gather row i from the other buffer.
// THIS ROUND'S ONLY CHANGE vs R14: output stores use __stcs (evict-first) —
// write-once data; bias L2 toward prompt writeback so the 512MB read stream
// keeps L2 residency. Identical values to identical addresses (hint only).
// PDL: mbarrier init + ramp overlap finish_kernel; wait before reading g_idx.
// ---------------------------------------------------------------------------
__global__ __launch_bounds__(AG_THREADS) void agather_kernel(
    const float* __restrict__ A, float* __restrict__ outA,
    const float* __restrict__ X, float* __restrict__ outX)
{
    extern __shared__ float sbuf[];                // 2 x 16384 floats (128KB)
    __shared__ unsigned long long mbar[2];

    const int tid = threadIdx.x;
    const int bid = blockIdx.x;

    uint32_t mb0 = (uint32_t)__cvta_generic_to_shared(&mbar[0]);
    uint32_t mb1 = (uint32_t)__cvta_generic_to_shared(&mbar[1]);
    uint32_t sbase = (uint32_t)__cvta_generic_to_shared(sbuf);

    if (tid == 0) {
        asm volatile("mbarrier.init.shared.b64 [%0], 1;" :: "r"(mb0));
        asm volatile("mbarrier.init.shared.b64 [%0], 1;" :: "r"(mb1));
        asm volatile("fence.proxy.async.shared::cta;" ::: "memory");
    }
    __syncthreads();

    pdl_wait();                                    // g_idx now visible

    const int niters = (K_SEL - bid + AG_BLOCKS - 1) / AG_BLOCKS;

    // prologue: prefetch row for it=0 into buffer 0
    if (tid == 0) {
        int row0 = g_idx[bid];
        const char* src = (const char*)(A + (size_t)row0 * N_ROWS);
        asm volatile("mbarrier.arrive.expect_tx.shared.b64 _, [%0], %1;"
                     :: "r"(mb0), "r"(ROW_BYTES) : "memory");
#pragma unroll
        for (int c = 0; c < 4; c++)
            asm volatile(
                "cp.async.bulk.shared::cluster.global.mbarrier::complete_tx::bytes "
                "[%0], [%1], %2, [%3];"
                :: "r"(sbase + c * 16384), "l"(src + c * 16384),
                   "r"(16384), "r"(mb0) : "memory");
    }

    for (int it = 0; it < niters; it++) {
        const int s = it & 1;
        const int p = bid + it * AG_BLOCKS;

        // prefetch row it+1 into the other buffer (fully consumed at the end
        // of iteration it-1 — guaranteed by that iteration's __syncthreads).
        const int itn = it + 1;
        if (itn < niters && tid == 0) {
            int nrow = g_idx[bid + itn * AG_BLOCKS];
            const char* src = (const char*)(A + (size_t)nrow * N_ROWS);
            uint32_t dst = sbase + (unsigned)(itn & 1) * ROW_BYTES;
            uint32_t m = (itn & 1) ? mb1 : mb0;
            asm volatile("mbarrier.arrive.expect_tx.shared.b64 _, [%0], %1;"
                         :: "r"(m), "r"(ROW_BYTES) : "memory");
#pragma unroll
            for (int c = 0; c < 4; c++)
                asm volatile(
                    "cp.async.bulk.shared::cluster.global.mbarrier::complete_tx::bytes "
                    "[%0], [%1], %2, [%3];"
                    :: "r"(dst + c * 16384), "l"(src + c * 16384),
                       "r"(16384), "r"(m) : "memory");
        }

        // wait for buffer s (phase parity = (it>>1)&1)
        {
            uint32_t m = s ? mb1 : mb0;
            unsigned ph = (unsigned)((it >> 1) & 1);
            unsigned done;
            asm volatile(
                "{\n\t.reg .pred p;\n\t"
                "mbarrier.try_wait.parity.acquire.cta.shared::cta.b64 p, [%1], %2;\n\t"
                "selp.b32 %0, 1, 0, p;\n\t}"
                : "=r"(done) : "r"(m), "r"(ph) : "memory");
            while (!done) {
                asm volatile(
                    "{\n\t.reg .pred p;\n\t"
                    "mbarrier.try_wait.parity.acquire.cta.shared::cta.b64 p, [%1], %2, 0x989680;\n\t"
                    "selp.b32 %0, 1, 0, p;\n\t}"
                    : "=r"(done) : "r"(m), "r"(ph) : "memory");
            }
        }

        const float* buf = sbuf + (size_t)s * N_ROWS;
        int row = g_idx[p];

        // folded X gather: 64 float4 = one X row (evict-first store)
        if (tid < F_DIM / 4) {
            float4 xv = ((const float4*)(X + (size_t)row * F_DIM))[tid];
            __stcs(((float4*)(outX + (size_t)p * F_DIM)) + tid, xv);
        }

        float4* dst = (float4*)(outA + (size_t)p * K_SEL);
        const int4* idx4 = (const int4*)g_idx;
#pragma unroll
        for (int t = 0; t < 2; t++) {
            int q4 = tid + AG_THREADS * t;         // quad index, coalesced
            int4 id = __ldg(idx4 + q4);
            float4 v;
            v.x = buf[id.x];
            v.y = buf[id.y];
            v.z = buf[id.z];
            v.w = buf[id.w];
            __stcs(dst + q4, v);                   // evict-first STG.128
        }

        __syncthreads();   // buffer s fully consumed; safe to overwrite next iter
    }
}

// ---------------------------------------------------------------------------
extern "C" void kernel_launch(void* const* d_in, const int* in_sizes, int n_in,
                              void* d_out, int out_size)
{
    const float* X  = (const float*)d_in[0];   // [16384, 256]
    const float* A  = (const float*)d_in[1];   // [16384, 16384]
    const float* sv = (const float*)d_in[2];   // [256, 1]
    float* out = (float*)d_out;

    cudaFuncSetAttribute(agather_kernel,
                         cudaFuncAttributeMaxDynamicSharedMemorySize,
                         2 * ROW_BYTES);

    // 1) scores + keys + bucket histogram (WIDE)
    scores_kernel<<<(N_ROWS * 32) / 256, 256>>>(X, sv);

    // 2) finish (PDL: launches early, waits for scores completion in-kernel)
    {
        cudaLaunchConfig_t cfg = {};
        cfg.gridDim  = dim3(FIN_BLOCKS, 1, 1);
        cfg.blockDim = dim3(FIN_THREADS, 1, 1);
        cudaLaunchAttribute attrs[1];
        attrs[0].id = cudaLaunchAttributeProgrammaticStreamSerialization;
        attrs[0].val.programmaticStreamSerializationAllowed = 1;
        cfg.attrs = attrs;
        cfg.numAttrs = 1;
        float* oidx = out + OUT_I_OFF;
        cudaLaunchKernelEx(&cfg, finish_kernel, oidx);
    }

    // 3) agather (PDL: ramps + inits mbarriers under finish, waits for g_idx)
    {
        cudaLaunchConfig_t cfg = {};
        cfg.gridDim  = dim3(AG_BLOCKS, 1, 1);
        cfg.blockDim = dim3(AG_THREADS, 1, 1);
        cfg.dynamicSmemBytes = 2 * ROW_BYTES;
        cudaLaunchAttribute attrs[1];
        attrs[0].id = cudaLaunchAttributeProgrammaticStreamSerialization;
        attrs[0].val.programmaticStreamSerializationAllowed = 1;
        cfg.attrs = attrs;
        cfg.numAttrs = 1;
        float* oA = out + OUT_A_OFF;
        float* oX = out + OUT_X_OFF;
        cudaLaunchKernelEx(&cfg, agather_kernel, A, oA, X, oX);
    }
}

// round 16
// speedup vs baseline: 1.0097x; 1.0097x over previous
#include <cuda_runtime.h>
#include <cuda_bf16.h>
#include <stdint.h>

// Problem constants
#define N_ROWS 16384
#define F_DIM  256
#define K_SEL  8192   // ceil(0.5 * 16384)
#define NBINS  16384  // top-14-bit buckets of the u64 sort key

#define FIN_BLOCKS 64
#define FIN_THREADS 256

#define AG_BLOCKS 148        // one persistent block per SM
#define AG_THREADS 1024
#define ROW_BYTES 65536      // one A row: 16384 f32

// Output layout (flat f32): X_pooled [K_SEL*F_DIM] | A_pooled [K_SEL*K_SEL] | idx [K_SEL]
#define OUT_X_OFF 0
#define OUT_A_OFF (K_SEL * F_DIM)                       // 2,097,152
#define OUT_I_OFF (OUT_A_OFF + (size_t)K_SEL * K_SEL)   // 69,206,016

// PDL intrinsics (sm_90+): let dependent grid launch early; consumer waits
// for producer completion (incl. memory flush) before touching its data.
__device__ __forceinline__ void pdl_trigger()
{
    asm volatile("griddepcontrol.launch_dependents;" ::: "memory");
}
__device__ __forceinline__ void pdl_wait()
{
    asm volatile("griddepcontrol.wait;" ::: "memory");
}

// Scratch (device globals: no allocations allowed).
// g_hist relies on zero-init at module load; finish_kernel re-zeros it after
// reading, so every launch leaves it zeroed (replay-safe).
__device__ unsigned long long g_keys[N_ROWS];    // per-row sort key
__device__ unsigned long long g_bkeys[N_ROWS];   // keys grouped by bucket
__device__ int g_hist[NBINS];
__device__ int g_base[NBINS];                    // bucket exclusive prefix
__device__ int g_cursor[NBINS];                  // scatter cursors (end after scatter)
__device__ unsigned g_bsum[FIN_BLOCKS];          // per-block bin totals
__device__ int g_idx[K_SEL];

// Monotonic grid barrier ticket. NEVER reset — correct across graph replays
// and ncu kernel replays because the goal is computed per-arrival.
__device__ unsigned long long g_ticket;

__device__ __forceinline__ void grid_sync_fin()
{
    __syncthreads();
    if (threadIdx.x == 0) {
        __threadfence();                               // release my writes
        unsigned long long t = atomicAdd(&g_ticket, 1ull) + 1ull;
        unsigned long long goal =
            ((t + FIN_BLOCKS - 1ull) / FIN_BLOCKS) * FIN_BLOCKS;
        unsigned long long cur;
        do {
            asm volatile("ld.acquire.gpu.u64 %0, [%1];"
                         : "=l"(cur) : "l"(&g_ticket));
        } while (cur < goal);
    }
    __syncthreads();
}

// ---------------------------------------------------------------------------
// Kernel 1 (WIDE): scores = X @ v ; sortable u64 keys; 14-bit histogram.
// One warp per row, lane-strided c = lane + 32*t, EXPLICIT rounded mul +
// rounded add (NO fma), xor shuffle tree — bit-matches the XLA reference
// reduction. key = (~orderedU32(score) << 32) | row : ascending key ==
// descending score, ties -> ascending row (lax.top_k). DO NOT TOUCH THE MATH.
// PDL: trigger at entry so finish_kernel can ramp up concurrently.
// ---------------------------------------------------------------------------
__global__ __launch_bounds__(256) void scores_kernel(
    const float* __restrict__ X, const float* __restrict__ sv)
{
    pdl_trigger();

    int gwarp = (blockIdx.x * blockDim.x + threadIdx.x) >> 5;
    int lane  = threadIdx.x & 31;
    if (gwarp >= N_ROWS) return;

    const float* xr = X + (size_t)gwarp * F_DIM;
    float acc = 0.0f;
#pragma unroll
    for (int t = 0; t < F_DIM / 32; t++) {
        int c = lane + 32 * t;
        acc = __fadd_rn(acc, __fmul_rn(__ldg(xr + c), __ldg(sv + c)));
    }
#pragma unroll
    for (int o = 16; o > 0; o >>= 1)
        acc = __fadd_rn(acc, __shfl_xor_sync(0xFFFFFFFFu, acc, o));

    if (lane == 0) {
        unsigned ub = __float_as_uint(acc);
        unsigned u = (ub & 0x80000000u) ? ~ub : (ub | 0x80000000u);
        unsigned long long key =
            ((unsigned long long)(~u) << 32) | (unsigned)gwarp;
        g_keys[gwarp] = key;
        atomicAdd(&g_hist[(int)(key >> 50)], 1);
    }
}

// ---------------------------------------------------------------------------
// Kernel 2 (PERSISTENT, tiny phases): 64 blocks x 256 threads, co-resident.
//   C: exclusive scan of 16384 bins (+ re-zero g_hist for next launch)
//   D: scatter keys into bucket-grouped order
//   E: exact rank = bucket_base + strict-less count within bucket; emit idx
// Intra-bucket scatter order is atomic-arrival order — harmless: ranking
// compares full unique keys, so the result is deterministic.
// PDL: trigger at entry (lets agather ramp), wait before reading g_hist.
// ---------------------------------------------------------------------------
__global__ __launch_bounds__(FIN_THREADS) void finish_kernel(
    float* __restrict__ out_idx)
{
    pdl_trigger();

    const int tid  = threadIdx.x;
    const int bid  = blockIdx.x;
    const int lane = tid & 31;
    const int wid  = tid >> 5;
    const int gbin = bid * FIN_THREADS + tid;      // 0..16383

    pdl_wait();                                    // scores data now visible

    // ---- Phase C: exclusive scan over 16384 bins -----------------------
    __shared__ unsigned wsum[8], wpre[8];
    __shared__ unsigned bpre_sh;
    unsigned excl;
    {
        unsigned v = (unsigned)g_hist[gbin];
        g_hist[gbin] = 0;                          // re-arm for next launch
        unsigned orig = v;
#pragma unroll
        for (int o = 1; o < 32; o <<= 1) {         // inclusive warp scan
            unsigned n = __shfl_up_sync(0xFFFFFFFFu, v, o);
            if (lane >= o) v += n;
        }
        if (lane == 31) wsum[wid] = v;
        __syncthreads();
        if (wid == 0 && lane < 8) {
            unsigned s = wsum[lane];
#pragma unroll
            for (int o = 1; o < 8; o <<= 1) {
                unsigned n = __shfl_up_sync(0xFFu, s, o);
                if (lane >= o) s += n;
            }
            wpre[lane] = s - wsum[lane];           // exclusive warp prefix
            if (lane == 7) g_bsum[bid] = s;        // block total
        }
        __syncthreads();
        excl = v - orig + wpre[wid];               // exclusive within block
    }
    grid_sync_fin();
    {
        // cross-block prefix: sum of g_bsum[0..bid)
        if (wid == 0) {
            unsigned s1 = (lane < bid) ? g_bsum[lane] : 0u;
            unsigned s2 = (32 + lane < bid) ? g_bsum[32 + lane] : 0u;
            unsigned s = s1 + s2;
#pragma unroll
            for (int o = 16; o > 0; o >>= 1)
                s += __shfl_xor_sync(0xFFFFFFFFu, s, o);
            if (lane == 0) bpre_sh = s;
        }
        __syncthreads();
        int base = (int)(bpre_sh + excl);
        g_base[gbin] = base;
        g_cursor[gbin] = base;
    }
    grid_sync_fin();

    // ---- Phase D: bucket-grouped scatter --------------------------------
    {
        unsigned long long key = g_keys[gbin];
        int b = (int)(key >> 50);
        int pos = atomicAdd(&g_cursor[b], 1);
        g_bkeys[pos] = key;
    }
    grid_sync_fin();

    // ---- Phase E: exact rank + emit -------------------------------------
    {
        unsigned long long key = g_bkeys[gbin];
        int b = (int)(key >> 50);
        int lo = g_base[b];
        int hi = g_cursor[b];                      // == end of bucket b

        int r = lo;
        int j = lo;
        for (; j + 4 <= hi; j += 4) {
            unsigned long long k0 = __ldg(&g_bkeys[j]);
            unsigned long long k1 = __ldg(&g_bkeys[j + 1]);
            unsigned long long k2 = __ldg(&g_bkeys[j + 2]);
            unsigned long long k3 = __ldg(&g_bkeys[j + 3]);
            r += (k0 < key) + (k1 < key) + (k2 < key) + (k3 < key);
        }
        for (; j < hi; j++)
            r += (__ldg(&g_bkeys[j]) < key);

        if (r < K_SEL) {
            int row = (int)(unsigned)(key & 0xFFFFFFFFull);
            g_idx[r] = row;
            out_idx[r] = (float)row;
        }
    }
}

// ---------------------------------------------------------------------------
// Kernel 3 (PERSISTENT, double-buffered TMA): A_pooled[p][q] = A[idx[p]][idx[q]]
// + folded X_pooled[p] = X[idx[p]].
// 148 blocks (1/SM) x 1024 threads. Two 64KB smem row buffers; one producer
// thread prefetches row i+1 via cp.async.bulk (mbarrier complete_tx) while
// all threads gather row i from the other buffer. Measured at 80.6% DRAM —
// the device's mixed 2:1 read:write stream ceiling for this traffic.
// PDL: mbarrier init + ramp overlap finish_kernel; wait before reading g_idx.
// ---------------------------------------------------------------------------
__global__ __launch_bounds__(AG_THREADS) void agather_kernel(
    const float* __restrict__ A, float* __restrict__ outA,
    const float* __restrict__ X, float* __restrict__ outX)
{
    extern __shared__ float sbuf[];                // 2 x 16384 floats (128KB)
    __shared__ unsigned long long mbar[2];

    const int tid = threadIdx.x;
    const int bid = blockIdx.x;

    uint32_t mb0 = (uint32_t)__cvta_generic_to_shared(&mbar[0]);
    uint32_t mb1 = (uint32_t)__cvta_generic_to_shared(&mbar[1]);
    uint32_t sbase = (uint32_t)__cvta_generic_to_shared(sbuf);

    if (tid == 0) {
        asm volatile("mbarrier.init.shared.b64 [%0], 1;" :: "r"(mb0));
        asm volatile("mbarrier.init.shared.b64 [%0], 1;" :: "r"(mb1));
        asm volatile("fence.proxy.async.shared::cta;" ::: "memory");
    }
    __syncthreads();

    pdl_wait();                                    // g_idx now visible

    const int niters = (K_SEL - bid + AG_BLOCKS - 1) / AG_BLOCKS;

    // prologue: prefetch row for it=0 into buffer 0
    if (tid == 0) {
        int row0 = g_idx[bid];
        const char* src = (const char*)(A + (size_t)row0 * N_ROWS);
        asm volatile("mbarrier.arrive.expect_tx.shared.b64 _, [%0], %1;"
                     :: "r"(mb0), "r"(ROW_BYTES) : "memory");
#pragma unroll
        for (int c = 0; c < 4; c++)
            asm volatile(
                "cp.async.bulk.shared::cluster.global.mbarrier::complete_tx::bytes "
                "[%0], [%1], %2, [%3];"
                :: "r"(sbase + c * 16384), "l"(src + c * 16384),
                   "r"(16384), "r"(mb0) : "memory");
    }

    for (int it = 0; it < niters; it++) {
        const int s = it & 1;
        const int p = bid + it * AG_BLOCKS;

        // prefetch row it+1 into the other buffer (fully consumed at the end
        // of iteration it-1 — guaranteed by that iteration's __syncthreads).
        const int itn = it + 1;
        if (itn < niters && tid == 0) {
            int nrow = g_idx[bid + itn * AG_BLOCKS];
            const char* src = (const char*)(A + (size_t)nrow * N_ROWS);
            uint32_t dst = sbase + (unsigned)(itn & 1) * ROW_BYTES;
            uint32_t m = (itn & 1) ? mb1 : mb0;
            asm volatile("mbarrier.arrive.expect_tx.shared.b64 _, [%0], %1;"
                         :: "r"(m), "r"(ROW_BYTES) : "memory");
#pragma unroll
            for (int c = 0; c < 4; c++)
                asm volatile(
                    "cp.async.bulk.shared::cluster.global.mbarrier::complete_tx::bytes "
                    "[%0], [%1], %2, [%3];"
                    :: "r"(dst + c * 16384), "l"(src + c * 16384),
                       "r"(16384), "r"(m) : "memory");
        }

        // wait for buffer s (phase parity = (it>>1)&1)
        {
            uint32_t m = s ? mb1 : mb0;
            unsigned ph = (unsigned)((it >> 1) & 1);
            unsigned done;
            asm volatile(
                "{\n\t.reg .pred p;\n\t"
                "mbarrier.try_wait.parity.acquire.cta.shared::cta.b64 p, [%1], %2;\n\t"
                "selp.b32 %0, 1, 0, p;\n\t}"
                : "=r"(done) : "r"(m), "r"(ph) : "memory");
            while (!done) {
                asm volatile(
                    "{\n\t.reg .pred p;\n\t"
                    "mbarrier.try_wait.parity.acquire.cta.shared::cta.b64 p, [%1], %2, 0x989680;\n\t"
                    "selp.b32 %0, 1, 0, p;\n\t}"
                    : "=r"(done) : "r"(m), "r"(ph) : "memory");
            }
        }

        const float* buf = sbuf + (size_t)s * N_ROWS;
        int row = g_idx[p];

        // folded X gather: 64 float4 = one X row
        if (tid < F_DIM / 4) {
            ((float4*)(outX + (size_t)p * F_DIM))[tid] =
                ((const float4*)(X + (size_t)row * F_DIM))[tid];
        }

        float4* dst = (float4*)(outA + (size_t)p * K_SEL);
        const int4* idx4 = (const int4*)g_idx;
#pragma unroll
        for (int t = 0; t < 2; t++) {
            int q4 = tid + AG_THREADS * t;         // quad index, coalesced
            int4 id = __ldg(idx4 + q4);
            float4 v;
            v.x = buf[id.x];
            v.y = buf[id.y];
            v.z = buf[id.z];
            v.w = buf[id.w];
            dst[q4] = v;
        }

        __syncthreads();   // buffer s fully consumed; safe to overwrite next iter
    }
}

// ---------------------------------------------------------------------------
extern "C" void kernel_launch(void* const* d_in, const int* in_sizes, int n_in,
                              void* d_out, int out_size)
{
    const float* X  = (const float*)d_in[0];   // [16384, 256]
    const float* A  = (const float*)d_in[1];   // [16384, 16384]
    const float* sv = (const float*)d_in[2];   // [256, 1]
    float* out = (float*)d_out;

    cudaFuncSetAttribute(agather_kernel,
                         cudaFuncAttributeMaxDynamicSharedMemorySize,
                         2 * ROW_BYTES);

    // 1) scores + keys + bucket histogram (WIDE)
    scores_kernel<<<(N_ROWS * 32) / 256, 256>>>(X, sv);

    // 2) finish (PDL: launches early, waits for scores completion in-kernel)
    {
        cudaLaunchConfig_t cfg = {};
        cfg.gridDim  = dim3(FIN_BLOCKS, 1, 1);
        cfg.blockDim = dim3(FIN_THREADS, 1, 1);
        cudaLaunchAttribute attrs[1];
        attrs[0].id = cudaLaunchAttributeProgrammaticStreamSerialization;
        attrs[0].val.programmaticStreamSerializationAllowed = 1;
        cfg.attrs = attrs;
        cfg.numAttrs = 1;
        float* oidx = out + OUT_I_OFF;
        cudaLaunchKernelEx(&cfg, finish_kernel, oidx);
    }

    // 3) agather (PDL: ramps + inits mbarriers under finish, waits for g_idx)
    {
        cudaLaunchConfig_t cfg = {};
        cfg.gridDim  = dim3(AG_BLOCKS, 1, 1);
        cfg.blockDim = dim3(AG_THREADS, 1, 1);
        cfg.dynamicSmemBytes = 2 * ROW_BYTES;
        cudaLaunchAttribute attrs[1];
        attrs[0].id = cudaLaunchAttributeProgrammaticStreamSerialization;
        attrs[0].val.programmaticStreamSerializationAllowed = 1;
        cfg.attrs = attrs;
        cfg.numAttrs = 1;
        float* oA = out + OUT_A_OFF;
        float* oX = out + OUT_X_OFF;
        cudaLaunchKernelEx(&cfg, agather_kernel, A, oA, X, oX);
    }
}